// round 2
// baseline (speedup 1.0000x reference)
#include <cuda_runtime.h>

#define NN 50000
#define NE_IN 800000
#define NE (NE_IN + NN)          // 850000 with self loops
#define DD 128
#define NG 64
#define NC 10
#define NL 5

// ---------------- static device scratch (no allocations allowed) ----------------
__device__ __align__(16) float g_bufA[NN * DD];
__device__ __align__(16) float g_bufB[NN * DD];
__device__ __align__(16) float g_xl[NN * DD];
__device__ __align__(16) float g_xr[NN * DD];
__device__ __align__(16) float g_Wpack[DD * 256];
__device__ __align__(16) float g_bpack[256];
__device__ int   g_rowptr[NN + 1];
__device__ int   g_cursor[NN + 1];
__device__ int   g_esrc[NE];
__device__ int   g_cnt[NN];
__device__ __align__(16) float g_pool[NG * DD];
__device__ float g_pcnt[NG];

// ---------------- init: zero accumulators ----------------
__global__ void init_kernel() {
    int i = blockIdx.x * blockDim.x + threadIdx.x;
    if (i < NN) g_cnt[i] = 0;
    if (i < NG * DD) g_pool[i] = 0.f;
    if (i < NG) g_pcnt[i] = 0.f;
}

// ---------------- CSR build ----------------
__global__ void count_kernel(const int* __restrict__ ei) {
    int e = blockIdx.x * blockDim.x + threadIdx.x;
    if (e >= NE) return;
    int d = (e < NE_IN) ? ei[NE_IN + e] : (e - NE_IN);
    atomicAdd(&g_cnt[d], 1);
}

__global__ void scan_kernel() {
    __shared__ int warpsum[32];
    __shared__ int s_carry;
    int tid = threadIdx.x;
    if (tid == 0) s_carry = 0;
    __syncthreads();
    for (int base = 0; base < NN; base += 1024) {
        int i = base + tid;
        int v = (i < NN) ? g_cnt[i] : 0;
        int x = v;
#pragma unroll
        for (int off = 1; off < 32; off <<= 1) {
            int y = __shfl_up_sync(0xffffffffu, x, off);
            if ((tid & 31) >= off) x += y;
        }
        if ((tid & 31) == 31) warpsum[tid >> 5] = x;
        __syncthreads();
        if (tid < 32) {
            int w = warpsum[tid];
            int xs = w;
#pragma unroll
            for (int off = 1; off < 32; off <<= 1) {
                int y = __shfl_up_sync(0xffffffffu, xs, off);
                if (tid >= off) xs += y;
            }
            warpsum[tid] = xs - w;   // exclusive warp offsets
        }
        __syncthreads();
        int incl = x + warpsum[tid >> 5];
        int excl = incl - v + s_carry;
        if (i < NN) { g_rowptr[i] = excl; g_cursor[i] = excl; }
        __syncthreads();
        if (tid == 1023) s_carry += incl;   // incl of last thread = block total
        __syncthreads();
    }
    if (tid == 0) { g_rowptr[NN] = s_carry; g_cursor[NN] = s_carry; }
}

__global__ void scatter_kernel(const int* __restrict__ ei) {
    int e = blockIdx.x * blockDim.x + threadIdx.x;
    if (e >= NE) return;
    int s, d;
    if (e < NE_IN) { s = ei[e]; d = ei[NE_IN + e]; }
    else           { s = e - NE_IN; d = s; }
    int pos = atomicAdd(&g_cursor[d], 1);
    g_esrc[pos] = s;
}

// ---------------- per-layer weight pack: [Wl | Wr] -> [128,256] ----------------
__global__ void pack_kernel(const float* __restrict__ Wl, const float* __restrict__ bl,
                            const float* __restrict__ Wr, const float* __restrict__ br,
                            int l) {
    int i = blockIdx.x * blockDim.x + threadIdx.x;
    if (i < DD * 256) {
        int k = i >> 8, j = i & 255;
        g_Wpack[i] = (j < DD) ? Wl[l * DD * DD + k * DD + j]
                              : Wr[l * DD * DD + k * DD + (j - DD)];
    } else if (i < DD * 256 + 256) {
        int j = i - DD * 256;
        g_bpack[j] = (j < DD) ? bl[l * DD + j] : br[l * DD + j - DD];
    }
}

// ---------------- fused GEMM: [xl | xr] = h @ [Wl | Wr] + [bl | br] ----------------
// BM=64, BN=64, BK=16, 256 threads, 4x4 per thread
__global__ void gemm_kernel(const float* __restrict__ Aext, int use_ext, int inbuf) {
    const float* A = use_ext ? Aext : (inbuf == 0 ? g_bufA : g_bufB);
    __shared__ float As[16][64];
    __shared__ float Bs[16][64];
    int tid = threadIdx.x;
    int bm0 = blockIdx.x * 64;
    int bn0 = blockIdx.y * 64;
    int arow = tid >> 2, ak = (tid & 3) << 2;
    int brow = tid >> 4, bcol = (tid & 15) << 2;
    int tx = (tid & 15) << 2, ty = (tid >> 4) << 2;
    int gr = bm0 + arow;
    bool arow_ok = (gr < NN);

    float acc[4][4];
#pragma unroll
    for (int r = 0; r < 4; r++)
#pragma unroll
        for (int c = 0; c < 4; c++) acc[r][c] = 0.f;

    for (int k0 = 0; k0 < DD; k0 += 16) {
        float4 a4 = make_float4(0.f, 0.f, 0.f, 0.f);
        if (arow_ok) a4 = *(const float4*)(A + gr * DD + k0 + ak);
        As[ak + 0][arow] = a4.x;
        As[ak + 1][arow] = a4.y;
        As[ak + 2][arow] = a4.z;
        As[ak + 3][arow] = a4.w;
        *(float4*)&Bs[brow][bcol] =
            *(const float4*)&g_Wpack[(k0 + brow) * 256 + bn0 + bcol];
        __syncthreads();
#pragma unroll
        for (int kk = 0; kk < 16; kk++) {
            float4 av = *(float4*)&As[kk][ty];
            float4 bv = *(float4*)&Bs[kk][tx];
            float a[4] = {av.x, av.y, av.z, av.w};
            float b[4] = {bv.x, bv.y, bv.z, bv.w};
#pragma unroll
            for (int r = 0; r < 4; r++)
#pragma unroll
                for (int c = 0; c < 4; c++) acc[r][c] += a[r] * b[c];
        }
        __syncthreads();
    }

    int col = bn0 + tx;
    float4 bb = *(const float4*)&g_bpack[col];
#pragma unroll
    for (int r = 0; r < 4; r++) {
        int row = bm0 + ty + r;
        if (row >= NN) continue;
        float4 v;
        v.x = acc[r][0] + bb.x;
        v.y = acc[r][1] + bb.y;
        v.z = acc[r][2] + bb.z;
        v.w = acc[r][3] + bb.w;
        float* dst = (col < DD) ? (g_xl + row * DD + col)
                                : (g_xr + row * DD + (col - DD));
        *(float4*)dst = v;
    }
}

// ---------------- GAT edge aggregation: one warp per dst node, online softmax ----------------
// lane L owns head h=L/4, channels 4*(L%4)..  -> flat feature index 4*L..4*L+3
__global__ void gat_kernel(const float* __restrict__ attb,
                           const float* __restrict__ biasb,
                           int outbuf) {
    int gw = (blockIdx.x * blockDim.x + threadIdx.x) >> 5;
    int lane = threadIdx.x & 31;
    if (gw >= NN) return;
    float* hout = (outbuf == 0) ? g_bufA : g_bufB;

    float4 att4 = *(const float4*)(attb + lane * 4);
    float4 xr4  = *(const float4*)(g_xr + gw * DD + lane * 4);
    int jb = g_rowptr[gw], je = g_rowptr[gw + 1];

    float m = -3.0e38f, s = 0.f;
    float4 acc = make_float4(0.f, 0.f, 0.f, 0.f);

    for (int j = jb; j < je; j++) {
        int src = g_esrc[j];
        float4 xl4 = *(const float4*)(g_xl + src * DD + lane * 4);
        float zx = xl4.x + xr4.x; zx = zx > 0.f ? zx : 0.2f * zx;
        float zy = xl4.y + xr4.y; zy = zy > 0.f ? zy : 0.2f * zy;
        float zz = xl4.z + xr4.z; zz = zz > 0.f ? zz : 0.2f * zz;
        float zw = xl4.w + xr4.w; zw = zw > 0.f ? zw : 0.2f * zw;
        float part = att4.x * zx + att4.y * zy + att4.z * zz + att4.w * zw;
        part += __shfl_xor_sync(0xffffffffu, part, 1);
        part += __shfl_xor_sync(0xffffffffu, part, 2);
        float p;
        if (part > m) {
            float r = __expf(m - part);
            s *= r;
            acc.x *= r; acc.y *= r; acc.z *= r; acc.w *= r;
            m = part;
            p = 1.f;
        } else {
            p = __expf(part - m);
        }
        s += p;
        acc.x += p * xl4.x;
        acc.y += p * xl4.y;
        acc.z += p * xl4.z;
        acc.w += p * xl4.w;
    }

    float inv = 1.f / s;
    float4 b4 = *(const float4*)(biasb + lane * 4);
    float ox = acc.x * inv + b4.x;
    float oy = acc.y * inv + b4.y;
    float oz = acc.z * inv + b4.z;
    float ow = acc.w * inv + b4.w;
    // ELU
    ox = ox > 0.f ? ox : (__expf(ox) - 1.f);
    oy = oy > 0.f ? oy : (__expf(oy) - 1.f);
    oz = oz > 0.f ? oz : (__expf(oz) - 1.f);
    ow = ow > 0.f ? ow : (__expf(ow) - 1.f);
    *(float4*)(hout + gw * DD + lane * 4) = make_float4(ox, oy, oz, ow);
}

// ---------------- global mean pool (atomic accumulate) ----------------
__global__ void pool_kernel(const int* __restrict__ batch) {
    int w = (blockIdx.x * blockDim.x + threadIdx.x) >> 5;
    int lane = threadIdx.x & 31;
    if (w >= NN) return;
    int g = batch[w];
    float4 v = *(const float4*)(g_bufA + w * DD + lane * 4);  // layer 4 output = bufA
    float* base = g_pool + g * DD + lane * 4;
    atomicAdd(base + 0, v.x);
    atomicAdd(base + 1, v.y);
    atomicAdd(base + 2, v.z);
    atomicAdd(base + 3, v.w);
    if (lane == 0) atomicAdd(&g_pcnt[g], 1.f);
}

// ---------------- classifier + log_softmax ----------------
__global__ void cls_kernel(const float* __restrict__ Wout,
                           const float* __restrict__ bout,
                           float* __restrict__ out) {
    __shared__ float slog[NG][NC];
    __shared__ float srow[NG];
    int t = threadIdx.x;   // 640 threads
    if (t < NG * NC) {
        int g = t / NC, c = t % NC;
        float inv = 1.f / fmaxf(g_pcnt[g], 1.f);
        float acc = 0.f;
        for (int k = 0; k < DD; k++) acc += g_pool[g * DD + k] * Wout[k * NC + c];
        slog[g][c] = acc * inv + bout[c];
    }
    __syncthreads();
    if (t < NG) {
        float mx = -3.0e38f;
        for (int c = 0; c < NC; c++) mx = fmaxf(mx, slog[t][c]);
        float ssum = 0.f;
        for (int c = 0; c < NC; c++) ssum += expf(slog[t][c] - mx);
        srow[t] = mx + logf(ssum);
    }
    __syncthreads();
    if (t < NG * NC) out[t] = slog[t / NC][t % NC] - srow[t / NC];
}

// ---------------- driver ----------------
extern "C" void kernel_launch(void* const* d_in, const int* in_sizes, int n_in,
                              void* d_out, int out_size) {
    const float* x     = (const float*)d_in[0];
    const int*   ei    = (const int*)  d_in[1];
    const int*   batch = (const int*)  d_in[2];
    const float* Wl    = (const float*)d_in[3];
    const float* bl    = (const float*)d_in[4];
    const float* Wr    = (const float*)d_in[5];
    const float* br    = (const float*)d_in[6];
    const float* att   = (const float*)d_in[7];
    const float* bias  = (const float*)d_in[8];
    const float* Wout  = (const float*)d_in[9];
    const float* bout  = (const float*)d_in[10];
    float* out = (float*)d_out;

    init_kernel<<<(NN + 255) / 256, 256>>>();
    count_kernel<<<(NE + 255) / 256, 256>>>(ei);
    scan_kernel<<<1, 1024>>>();
    scatter_kernel<<<(NE + 255) / 256, 256>>>(ei);

    for (int l = 0; l < NL; l++) {
        pack_kernel<<<(DD * 256 + 256 + 255) / 256, 256>>>(Wl, bl, Wr, br, l);
        int use_ext = (l == 0) ? 1 : 0;
        int inbuf   = (l % 2 == 0) ? 1 : 0;   // input buffer for l>0
        dim3 ggrid((NN + 63) / 64, 4);
        gemm_kernel<<<ggrid, 256>>>(x, use_ext, inbuf);
        int outbuf = (l % 2 == 0) ? 0 : 1;
        gat_kernel<<<(NN * 32 + 255) / 256, 256>>>(att + l * DD, bias + l * DD, outbuf);
    }

    pool_kernel<<<(NN * 32 + 255) / 256, 256>>>(batch);
    cls_kernel<<<1, 640>>>(Wout, bout, out);
}

// round 3
// speedup vs baseline: 1.8264x; 1.8264x over previous
#include <cuda_runtime.h>
#include <cstdint>

#define NN 50000
#define NE_IN 800000
#define NE (NE_IN + NN)
#define DD 128
#define NG 64
#define NC 10
#define NL 5

#define SCAN_BLOCKS ((NN + 1023) / 1024)

// ---------------- static device scratch ----------------
__device__ __align__(16) float g_bufA[NN * DD];
__device__ __align__(16) float g_bufB[NN * DD];
__device__ __align__(16) float g_xl[NN * DD];
__device__ __align__(16) float g_xr[NN * DD];
__device__ __align__(16) float g_Wpack[NL * DD * 256];
__device__ __align__(16) float g_bpack[NL * 256];
__device__ int   g_rowptr[NN + 1];
__device__ int   g_cursor[NN];
__device__ int   g_esrc[NE];
__device__ int   g_cnt[NN];
__device__ int   g_bsum[64];
__device__ __align__(16) float g_pool[NG * DD];
__device__ float g_pcnt[NG];

// ---------------- init ----------------
__global__ void init_kernel() {
    int i = blockIdx.x * blockDim.x + threadIdx.x;
    if (i < NN) g_cnt[i] = 0;
    if (i < NG * DD) g_pool[i] = 0.f;
    if (i < NG) g_pcnt[i] = 0.f;
}

// ---------------- CSR build ----------------
__global__ void count_kernel(const int* __restrict__ ei) {
    int e = blockIdx.x * blockDim.x + threadIdx.x;
    if (e >= NE) return;
    int d = (e < NE_IN) ? ei[NE_IN + e] : (e - NE_IN);
    atomicAdd(&g_cnt[d], 1);
}

__global__ void scan1_kernel() {
    __shared__ int wsum[32];
    int tid = threadIdx.x;
    int i = blockIdx.x * 1024 + tid;
    int v = (i < NN) ? g_cnt[i] : 0;
    int x = v;
#pragma unroll
    for (int off = 1; off < 32; off <<= 1) {
        int y = __shfl_up_sync(0xffffffffu, x, off);
        if ((tid & 31) >= off) x += y;
    }
    if ((tid & 31) == 31) wsum[tid >> 5] = x;
    __syncthreads();
    if (tid < 32) {
        int w = wsum[tid];
        int xs = w;
#pragma unroll
        for (int off = 1; off < 32; off <<= 1) {
            int y = __shfl_up_sync(0xffffffffu, xs, off);
            if (tid >= off) xs += y;
        }
        wsum[tid] = xs - w;
    }
    __syncthreads();
    int incl = x + wsum[tid >> 5];
    if (i < NN) g_rowptr[i] = incl - v;      // block-local exclusive
    if (tid == 1023) g_bsum[blockIdx.x] = incl;
}

__global__ void scan2_kernel() {
    if (threadIdx.x == 0) {
        int acc = 0;
        for (int b = 0; b < SCAN_BLOCKS; b++) { int t = g_bsum[b]; g_bsum[b] = acc; acc += t; }
    }
}

__global__ void scan3_kernel() {
    int i = blockIdx.x * 1024 + threadIdx.x;
    if (i < NN) {
        int r = g_rowptr[i] + g_bsum[blockIdx.x];
        g_rowptr[i] = r;
        g_cursor[i] = r;
    }
    if (i == 0) g_rowptr[NN] = NE;
}

__global__ void scatter_kernel(const int* __restrict__ ei) {
    int e = blockIdx.x * blockDim.x + threadIdx.x;
    if (e >= NE) return;
    int s, d;
    if (e < NE_IN) { s = ei[e]; d = ei[NE_IN + e]; }
    else           { s = e - NE_IN; d = s; }
    int pos = atomicAdd(&g_cursor[d], 1);
    g_esrc[pos] = s;
}

// ---------------- pack ALL layers' weights once ----------------
__global__ void pack_kernel(const float* __restrict__ Wl, const float* __restrict__ bl,
                            const float* __restrict__ Wr, const float* __restrict__ br) {
    int i = blockIdx.x * blockDim.x + threadIdx.x;
    int WTOT = NL * DD * 256;
    if (i < WTOT) {
        int l = i / (DD * 256);
        int rem = i - l * DD * 256;
        int k = rem >> 8, j = rem & 255;
        g_Wpack[i] = (j < DD) ? Wl[(l * DD + k) * DD + j]
                              : Wr[(l * DD + k) * DD + (j - DD)];
    } else if (i < WTOT + NL * 256) {
        int r = i - WTOT;
        int l = r >> 8, j = r & 255;
        g_bpack[r] = (j < DD) ? bl[l * DD + j] : br[l * DD + j - DD];
    }
}

// ---------------- tf32 tensor-core GEMM ----------------
// C[M,256] = A[M,128] @ Wpack[l][128,256] + bpack[l]; split cols -> g_xl / g_xr
// BM=128 BN=64 BK=16, 256 threads (8 warps, 4x2), warp tile 32x32, mma m16n8k8 tf32
#define GBM 128
#define GBN 64
#define GBK 16

__device__ __forceinline__ uint32_t f2tf32(float f) {
    uint32_t u;
    asm volatile("cvt.rna.tf32.f32 %0, %1;" : "=r"(u) : "f"(f));
    return u;
}
__device__ __forceinline__ void cpa16(void* smem, const void* g) {
    unsigned sa = (unsigned)__cvta_generic_to_shared(smem);
    asm volatile("cp.async.cg.shared.global [%0], [%1], 16;" :: "r"(sa), "l"(g));
}
__device__ __forceinline__ void mma8(float* c, const uint32_t* a, const uint32_t* b) {
    asm volatile(
        "mma.sync.aligned.m16n8k8.row.col.f32.tf32.tf32.f32 "
        "{%0,%1,%2,%3},{%4,%5,%6,%7},{%8,%9},{%0,%1,%2,%3};"
        : "+f"(c[0]), "+f"(c[1]), "+f"(c[2]), "+f"(c[3])
        : "r"(a[0]), "r"(a[1]), "r"(a[2]), "r"(a[3]), "r"(b[0]), "r"(b[1]));
}

__global__ __launch_bounds__(256) void gemm_tc_kernel(const float* __restrict__ xext, int l) {
    const float* A = (l == 0) ? xext : ((l & 1) ? g_bufA : g_bufB);
    __shared__ float As[2][GBM][GBK + 4];   // stride 20
    __shared__ float Bs[2][GBK][GBN + 4];   // stride 68

    int tid  = threadIdx.x;
    int lane = tid & 31;
    int warp = tid >> 5;
    int wm = warp >> 1, wn = warp & 1;
    int g = lane >> 2, t = lane & 3;
    int bm0 = blockIdx.x * GBM;

    const float* Wb = g_Wpack + l * (DD * 256) + blockIdx.y * GBN;

    float acc[2][4][4];
#pragma unroll
    for (int mt = 0; mt < 2; mt++)
#pragma unroll
        for (int nt = 0; nt < 4; nt++)
#pragma unroll
            for (int c = 0; c < 4; c++) acc[mt][nt][c] = 0.f;

    // stage loader
    auto load_stage = [&](int buf, int k0) {
#pragma unroll
        for (int i = 0; i < 2; i++) {
            int idx = tid + i * 256;
            int row = idx >> 2, q = idx & 3;
            int gr = bm0 + row; if (gr >= NN) gr = NN - 1;
            cpa16(&As[buf][row][q * 4], A + (size_t)gr * DD + k0 + q * 4);
        }
        {
            int row = tid >> 4, q = tid & 15;
            cpa16(&Bs[buf][row][q * 4], Wb + (k0 + row) * 256 + q * 4);
        }
        asm volatile("cp.async.commit_group;");
    };

    load_stage(0, 0);

    int buf = 0;
#pragma unroll
    for (int kt = 0; kt < DD / GBK; kt++) {
        if (kt + 1 < DD / GBK) {
            load_stage(buf ^ 1, (kt + 1) * GBK);
            asm volatile("cp.async.wait_group 1;");
        } else {
            asm volatile("cp.async.wait_group 0;");
        }
        __syncthreads();

#pragma unroll
        for (int ks = 0; ks < 2; ks++) {
            int kk = ks * 8;
            uint32_t af[2][4];
#pragma unroll
            for (int mt = 0; mt < 2; mt++) {
                int r0 = wm * 32 + mt * 16 + g;
                af[mt][0] = f2tf32(As[buf][r0][kk + t]);
                af[mt][1] = f2tf32(As[buf][r0 + 8][kk + t]);
                af[mt][2] = f2tf32(As[buf][r0][kk + t + 4]);
                af[mt][3] = f2tf32(As[buf][r0 + 8][kk + t + 4]);
            }
            uint32_t bf[4][2];
#pragma unroll
            for (int nt = 0; nt < 4; nt++) {
                int c0 = wn * 32 + nt * 8 + g;
                bf[nt][0] = f2tf32(Bs[buf][kk + t][c0]);
                bf[nt][1] = f2tf32(Bs[buf][kk + t + 4][c0]);
            }
#pragma unroll
            for (int mt = 0; mt < 2; mt++)
#pragma unroll
                for (int nt = 0; nt < 4; nt++)
                    mma8(acc[mt][nt], af[mt], bf[nt]);
        }
        __syncthreads();
        buf ^= 1;
    }

    // epilogue
    int cbase = blockIdx.y * GBN + wn * 32;
    const float* bp = g_bpack + l * 256;
    float* obase = (blockIdx.y < 2) ? g_xl : g_xr;
    int coff = (blockIdx.y < 2) ? cbase : cbase - DD;
#pragma unroll
    for (int mt = 0; mt < 2; mt++) {
        int r0 = bm0 + wm * 32 + mt * 16 + g;
#pragma unroll
        for (int nt = 0; nt < 4; nt++) {
            int cb = cbase + nt * 8 + 2 * t;
            int c  = coff + nt * 8 + 2 * t;
            float bx = bp[cb], by = bp[cb + 1];
            if (r0 < NN) {
                float2 v = make_float2(acc[mt][nt][0] + bx, acc[mt][nt][1] + by);
                *(float2*)(obase + (size_t)r0 * DD + c) = v;
            }
            if (r0 + 8 < NN) {
                float2 v = make_float2(acc[mt][nt][2] + bx, acc[mt][nt][3] + by);
                *(float2*)(obase + (size_t)(r0 + 8) * DD + c) = v;
            }
        }
    }
}

// ---------------- GAT edge aggregation ----------------
// one warp per dst node; lane = slot(=lane>>3)*8 + head(=lane&7)
// 4 edges processed per iteration, no shuffles in the hot loop
__device__ __forceinline__ float lrl(float z) { return z > 0.f ? z : 0.2f * z; }

__global__ __launch_bounds__(256) void gat_kernel(const float* __restrict__ attb,
                                                  const float* __restrict__ biasb,
                                                  int outbuf) {
    int gw = (blockIdx.x * blockDim.x + threadIdx.x) >> 5;
    int lane = threadIdx.x & 31;
    if (gw >= NN) return;
    float* hout = (outbuf == 0) ? g_bufA : g_bufB;

    int slot = lane >> 3, h = lane & 7;
    const float4* ap = (const float4*)(attb + h * 16);
    float4 at0 = ap[0], at1 = ap[1], at2 = ap[2], at3 = ap[3];
    const float4* xp = (const float4*)(g_xr + (size_t)gw * DD + h * 16);
    float4 xr0 = xp[0], xr1 = xp[1], xr2 = xp[2], xr3 = xp[3];

    int jb = g_rowptr[gw], je = g_rowptr[gw + 1];
    int nIter = (je - jb + 3) >> 2;

    float m = -3.0e38f, s = 0.f;
    float4 a0 = make_float4(0.f, 0.f, 0.f, 0.f), a1 = a0, a2 = a0, a3 = a0;

    for (int it = 0; it < nIter; it++) {
        int j = jb + it * 4 + slot;
        bool act = (j < je);
        int jj = act ? j : (je - 1);
        int src = g_esrc[jj];
        const float4* lp = (const float4*)(g_xl + (size_t)src * DD + h * 16);
        float4 x0 = lp[0], x1 = lp[1], x2 = lp[2], x3 = lp[3];

        float d = 0.f;
        d += at0.x * lrl(x0.x + xr0.x); d += at0.y * lrl(x0.y + xr0.y);
        d += at0.z * lrl(x0.z + xr0.z); d += at0.w * lrl(x0.w + xr0.w);
        d += at1.x * lrl(x1.x + xr1.x); d += at1.y * lrl(x1.y + xr1.y);
        d += at1.z * lrl(x1.z + xr1.z); d += at1.w * lrl(x1.w + xr1.w);
        d += at2.x * lrl(x2.x + xr2.x); d += at2.y * lrl(x2.y + xr2.y);
        d += at2.z * lrl(x2.z + xr2.z); d += at2.w * lrl(x2.w + xr2.w);
        d += at3.x * lrl(x3.x + xr3.x); d += at3.y * lrl(x3.y + xr3.y);
        d += at3.z * lrl(x3.z + xr3.z); d += at3.w * lrl(x3.w + xr3.w);

        float part = act ? d : -3.0e38f;
        float nm = fmaxf(m, part);
        float r = __expf(m - nm);
        float p = act ? __expf(d - nm) : 0.f;
        s = s * r + p;
        a0.x = a0.x * r + p * x0.x; a0.y = a0.y * r + p * x0.y;
        a0.z = a0.z * r + p * x0.z; a0.w = a0.w * r + p * x0.w;
        a1.x = a1.x * r + p * x1.x; a1.y = a1.y * r + p * x1.y;
        a1.z = a1.z * r + p * x1.z; a1.w = a1.w * r + p * x1.w;
        a2.x = a2.x * r + p * x2.x; a2.y = a2.y * r + p * x2.y;
        a2.z = a2.z * r + p * x2.z; a2.w = a2.w * r + p * x2.w;
        a3.x = a3.x * r + p * x3.x; a3.y = a3.y * r + p * x3.y;
        a3.z = a3.z * r + p * x3.z; a3.w = a3.w * r + p * x3.w;
        m = nm;
    }

    // merge the 4 slots (lanes xor 8, xor 16)
#pragma unroll
    for (int off = 8; off <= 16; off <<= 1) {
        float mo = __shfl_xor_sync(0xffffffffu, m, off);
        float so = __shfl_xor_sync(0xffffffffu, s, off);
        float nm = fmaxf(m, mo);
        float r1 = __expf(m - nm);
        float r2 = __expf(mo - nm);
        s = s * r1 + so * r2;
#define MRG(c) c = c * r1 + __shfl_xor_sync(0xffffffffu, c, off) * r2
        MRG(a0.x); MRG(a0.y); MRG(a0.z); MRG(a0.w);
        MRG(a1.x); MRG(a1.y); MRG(a1.z); MRG(a1.w);
        MRG(a2.x); MRG(a2.y); MRG(a2.z); MRG(a2.w);
        MRG(a3.x); MRG(a3.y); MRG(a3.z); MRG(a3.w);
#undef MRG
        m = nm;
    }

    if (slot == 0) {
        float inv = 1.f / s;
        const float4* bp = (const float4*)(biasb + h * 16);
        float4 b0 = bp[0], b1 = bp[1], b2 = bp[2], b3 = bp[3];
        float4 o0, o1, o2, o3;
#define FIN(o, a, b) \
        o.x = a.x * inv + b.x; o.x = o.x > 0.f ? o.x : (__expf(o.x) - 1.f); \
        o.y = a.y * inv + b.y; o.y = o.y > 0.f ? o.y : (__expf(o.y) - 1.f); \
        o.z = a.z * inv + b.z; o.z = o.z > 0.f ? o.z : (__expf(o.z) - 1.f); \
        o.w = a.w * inv + b.w; o.w = o.w > 0.f ? o.w : (__expf(o.w) - 1.f)
        FIN(o0, a0, b0); FIN(o1, a1, b1); FIN(o2, a2, b2); FIN(o3, a3, b3);
#undef FIN
        float4* op = (float4*)(hout + (size_t)gw * DD + h * 16);
        op[0] = o0; op[1] = o1; op[2] = o2; op[3] = o3;
    }
}

// ---------------- global mean pool ----------------
__global__ void pool_kernel(const int* __restrict__ batch) {
    int w = (blockIdx.x * blockDim.x + threadIdx.x) >> 5;
    int lane = threadIdx.x & 31;
    if (w >= NN) return;
    int g = batch[w];
    float4 v = *(const float4*)(g_bufA + (size_t)w * DD + lane * 4);
    float* base = g_pool + g * DD + lane * 4;
    atomicAdd(base + 0, v.x);
    atomicAdd(base + 1, v.y);
    atomicAdd(base + 2, v.z);
    atomicAdd(base + 3, v.w);
    if (lane == 0) atomicAdd(&g_pcnt[g], 1.f);
}

// ---------------- classifier + log_softmax ----------------
__global__ void cls_kernel(const float* __restrict__ Wout,
                           const float* __restrict__ bout,
                           float* __restrict__ out) {
    __shared__ float slog[NG][NC];
    __shared__ float srow[NG];
    int t = threadIdx.x;
    if (t < NG * NC) {
        int g = t / NC, c = t % NC;
        float inv = 1.f / fmaxf(g_pcnt[g], 1.f);
        float acc = 0.f;
        for (int k = 0; k < DD; k++) acc += g_pool[g * DD + k] * Wout[k * NC + c];
        slog[g][c] = acc * inv + bout[c];
    }
    __syncthreads();
    if (t < NG) {
        float mx = -3.0e38f;
        for (int c = 0; c < NC; c++) mx = fmaxf(mx, slog[t][c]);
        float ssum = 0.f;
        for (int c = 0; c < NC; c++) ssum += expf(slog[t][c] - mx);
        srow[t] = mx + logf(ssum);
    }
    __syncthreads();
    if (t < NG * NC) out[t] = slog[t / NC][t % NC] - srow[t / NC];
}

// ---------------- driver ----------------
extern "C" void kernel_launch(void* const* d_in, const int* in_sizes, int n_in,
                              void* d_out, int out_size) {
    const float* x     = (const float*)d_in[0];
    const int*   ei    = (const int*)  d_in[1];
    const int*   batch = (const int*)  d_in[2];
    const float* Wl    = (const float*)d_in[3];
    const float* bl    = (const float*)d_in[4];
    const float* Wr    = (const float*)d_in[5];
    const float* br    = (const float*)d_in[6];
    const float* att   = (const float*)d_in[7];
    const float* bias  = (const float*)d_in[8];
    const float* Wout  = (const float*)d_in[9];
    const float* bout  = (const float*)d_in[10];
    float* out = (float*)d_out;

    init_kernel<<<(NN + 255) / 256, 256>>>();
    count_kernel<<<(NE + 255) / 256, 256>>>(ei);
    scan1_kernel<<<SCAN_BLOCKS, 1024>>>();
    scan2_kernel<<<1, 32>>>();
    scan3_kernel<<<SCAN_BLOCKS, 1024>>>();
    scatter_kernel<<<(NE + 255) / 256, 256>>>(ei);
    pack_kernel<<<(NL * DD * 256 + NL * 256 + 255) / 256, 256>>>(Wl, bl, Wr, br);

    dim3 ggrid((NN + GBM - 1) / GBM, 4);
    for (int l = 0; l < NL; l++) {
        gemm_tc_kernel<<<ggrid, 256>>>(x, l);
        int outbuf = (l % 2 == 0) ? 0 : 1;
        gat_kernel<<<(NN * 32 + 255) / 256, 256>>>(att + l * DD, bias + l * DD, outbuf);
    }

    pool_kernel<<<(NN * 32 + 255) / 256, 256>>>(batch);
    cls_kernel<<<1, 640>>>(Wout, bout, out);
}

// round 4
// speedup vs baseline: 1.8419x; 1.0085x over previous
#include <cuda_runtime.h>
#include <cstdint>

#define NN 50000
#define NE_IN 800000
#define NE (NE_IN + NN)
#define DD 128
#define NG 64
#define NC 10
#define NL 5

#define SCAN_BLOCKS ((NN + 1023) / 1024)

// ---------------- static device scratch ----------------
__device__ __align__(16) float g_bufA[NN * DD];
__device__ __align__(16) float g_bufB[NN * DD];
__device__ __align__(16) float g_xl[NN * DD];
__device__ __align__(16) float g_xr[NN * DD];
__device__ __align__(16) float g_Wpack[NL * DD * 256];
__device__ __align__(16) float g_bpack[NL * 256];
__device__ int   g_rowptr[NN + 1];
__device__ int   g_cursor[NN];
__device__ int   g_esrc[NE];
__device__ int   g_cnt[NN];
__device__ int   g_bsum[64];
__device__ __align__(16) float g_pool[NG * DD];
__device__ float g_pcnt[NG];

__device__ __forceinline__ uint32_t f2tf32(float f) {
    uint32_t u;
    asm volatile("cvt.rna.tf32.f32 %0, %1;" : "=r"(u) : "f"(f));
    return u;
}
__device__ __forceinline__ float f2tf32f(float f) {
    uint32_t u = f2tf32(f);
    return __uint_as_float(u);
}

// ---------------- init ----------------
__global__ void init_kernel() {
    int i = blockIdx.x * blockDim.x + threadIdx.x;
    if (i < NN) g_cnt[i] = 0;
    if (i < NG * DD) g_pool[i] = 0.f;
    if (i < NG) g_pcnt[i] = 0.f;
}

// ---------------- round x (layer-0 input) into g_bufB as tf32 ----------------
__global__ void roundx_kernel(const float* __restrict__ x) {
    int i = blockIdx.x * blockDim.x + threadIdx.x;
    if (i < NN * DD / 4) {
        float4 v = ((const float4*)x)[i];
        v.x = f2tf32f(v.x); v.y = f2tf32f(v.y);
        v.z = f2tf32f(v.z); v.w = f2tf32f(v.w);
        ((float4*)g_bufB)[i] = v;
    }
}

// ---------------- CSR build ----------------
__global__ void count_kernel(const int* __restrict__ ei) {
    int e = blockIdx.x * blockDim.x + threadIdx.x;
    if (e >= NE) return;
    int d = (e < NE_IN) ? ei[NE_IN + e] : (e - NE_IN);
    atomicAdd(&g_cnt[d], 1);
}

__global__ void scan1_kernel() {
    __shared__ int wsum[32];
    int tid = threadIdx.x;
    int i = blockIdx.x * 1024 + tid;
    int v = (i < NN) ? g_cnt[i] : 0;
    int x = v;
#pragma unroll
    for (int off = 1; off < 32; off <<= 1) {
        int y = __shfl_up_sync(0xffffffffu, x, off);
        if ((tid & 31) >= off) x += y;
    }
    if ((tid & 31) == 31) wsum[tid >> 5] = x;
    __syncthreads();
    if (tid < 32) {
        int w = wsum[tid];
        int xs = w;
#pragma unroll
        for (int off = 1; off < 32; off <<= 1) {
            int y = __shfl_up_sync(0xffffffffu, xs, off);
            if (tid >= off) xs += y;
        }
        wsum[tid] = xs - w;
    }
    __syncthreads();
    int incl = x + wsum[tid >> 5];
    if (i < NN) g_rowptr[i] = incl - v;
    if (tid == 1023) g_bsum[blockIdx.x] = incl;
}

__global__ void scan2_kernel() {
    if (threadIdx.x == 0) {
        int acc = 0;
        for (int b = 0; b < SCAN_BLOCKS; b++) { int t = g_bsum[b]; g_bsum[b] = acc; acc += t; }
    }
}

__global__ void scan3_kernel() {
    int i = blockIdx.x * 1024 + threadIdx.x;
    if (i < NN) {
        int r = g_rowptr[i] + g_bsum[blockIdx.x];
        g_rowptr[i] = r;
        g_cursor[i] = r;
    }
    if (i == 0) g_rowptr[NN] = NE;
}

__global__ void scatter_kernel(const int* __restrict__ ei) {
    int e = blockIdx.x * blockDim.x + threadIdx.x;
    if (e >= NE) return;
    int s, d;
    if (e < NE_IN) { s = ei[e]; d = ei[NE_IN + e]; }
    else           { s = e - NE_IN; d = s; }
    int pos = atomicAdd(&g_cursor[d], 1);
    g_esrc[pos] = s;
}

// ---------------- pack weights (tf32-rounded) ----------------
__global__ void pack_kernel(const float* __restrict__ Wl, const float* __restrict__ bl,
                            const float* __restrict__ Wr, const float* __restrict__ br) {
    int i = blockIdx.x * blockDim.x + threadIdx.x;
    int WTOT = NL * DD * 256;
    if (i < WTOT) {
        int l = i / (DD * 256);
        int rem = i - l * DD * 256;
        int k = rem >> 8, j = rem & 255;
        float w = (j < DD) ? Wl[(l * DD + k) * DD + j]
                           : Wr[(l * DD + k) * DD + (j - DD)];
        g_Wpack[i] = f2tf32f(w);
    } else if (i < WTOT + NL * 256) {
        int r = i - WTOT;
        int l = r >> 8, j = r & 255;
        g_bpack[r] = (j < DD) ? bl[l * DD + j] : br[l * DD + j - DD];
    }
}

// ---------------- tf32 tensor-core GEMM (operands pre-rounded) ----------------
#define GBM 128
#define GBN 64
#define GBK 16

__device__ __forceinline__ void cpa16(void* smem, const void* g) {
    unsigned sa = (unsigned)__cvta_generic_to_shared(smem);
    asm volatile("cp.async.cg.shared.global [%0], [%1], 16;" :: "r"(sa), "l"(g));
}
__device__ __forceinline__ void mma8(float* c, const uint32_t* a, const uint32_t* b) {
    asm volatile(
        "mma.sync.aligned.m16n8k8.row.col.f32.tf32.tf32.f32 "
        "{%0,%1,%2,%3},{%4,%5,%6,%7},{%8,%9},{%0,%1,%2,%3};"
        : "+f"(c[0]), "+f"(c[1]), "+f"(c[2]), "+f"(c[3])
        : "r"(a[0]), "r"(a[1]), "r"(a[2]), "r"(a[3]), "r"(b[0]), "r"(b[1]));
}

__global__ __launch_bounds__(256) void gemm_tc_kernel(int l) {
    const float* A = (l & 1) ? g_bufA : g_bufB;   // l=0 reads pre-rounded x in bufB
    __shared__ float As[2][GBM][GBK + 4];
    __shared__ float Bs[2][GBK][GBN + 4];

    int tid  = threadIdx.x;
    int lane = tid & 31;
    int warp = tid >> 5;
    int wm = warp >> 1, wn = warp & 1;
    int g = lane >> 2, t = lane & 3;
    int bm0 = blockIdx.x * GBM;

    const float* Wb = g_Wpack + l * (DD * 256) + blockIdx.y * GBN;

    float acc[2][4][4];
#pragma unroll
    for (int mt = 0; mt < 2; mt++)
#pragma unroll
        for (int nt = 0; nt < 4; nt++)
#pragma unroll
            for (int c = 0; c < 4; c++) acc[mt][nt][c] = 0.f;

    auto load_stage = [&](int buf, int k0) {
#pragma unroll
        for (int i = 0; i < 2; i++) {
            int idx = tid + i * 256;
            int row = idx >> 2, q = idx & 3;
            int gr = bm0 + row; if (gr >= NN) gr = NN - 1;
            cpa16(&As[buf][row][q * 4], A + (size_t)gr * DD + k0 + q * 4);
        }
        {
            int row = tid >> 4, q = tid & 15;
            cpa16(&Bs[buf][row][q * 4], Wb + (k0 + row) * 256 + q * 4);
        }
        asm volatile("cp.async.commit_group;");
    };

    load_stage(0, 0);

    int buf = 0;
#pragma unroll
    for (int kt = 0; kt < DD / GBK; kt++) {
        if (kt + 1 < DD / GBK) {
            load_stage(buf ^ 1, (kt + 1) * GBK);
            asm volatile("cp.async.wait_group 1;");
        } else {
            asm volatile("cp.async.wait_group 0;");
        }
        __syncthreads();

#pragma unroll
        for (int ks = 0; ks < 2; ks++) {
            int kk = ks * 8;
            uint32_t af[2][4];
#pragma unroll
            for (int mt = 0; mt < 2; mt++) {
                int r0 = wm * 32 + mt * 16 + g;
                af[mt][0] = *(const uint32_t*)&As[buf][r0][kk + t];
                af[mt][1] = *(const uint32_t*)&As[buf][r0 + 8][kk + t];
                af[mt][2] = *(const uint32_t*)&As[buf][r0][kk + t + 4];
                af[mt][3] = *(const uint32_t*)&As[buf][r0 + 8][kk + t + 4];
            }
            uint32_t bf[4][2];
#pragma unroll
            for (int nt = 0; nt < 4; nt++) {
                int c0 = wn * 32 + nt * 8 + g;
                bf[nt][0] = *(const uint32_t*)&Bs[buf][kk + t][c0];
                bf[nt][1] = *(const uint32_t*)&Bs[buf][kk + t + 4][c0];
            }
#pragma unroll
            for (int mt = 0; mt < 2; mt++)
#pragma unroll
                for (int nt = 0; nt < 4; nt++)
                    mma8(acc[mt][nt], af[mt], bf[nt]);
        }
        __syncthreads();
        buf ^= 1;
    }

    int cbase = blockIdx.y * GBN + wn * 32;
    const float* bp = g_bpack + l * 256;
    float* obase = (blockIdx.y < 2) ? g_xl : g_xr;
    int coff = (blockIdx.y < 2) ? cbase : cbase - DD;
#pragma unroll
    for (int mt = 0; mt < 2; mt++) {
        int r0 = bm0 + wm * 32 + mt * 16 + g;
#pragma unroll
        for (int nt = 0; nt < 4; nt++) {
            int cb = cbase + nt * 8 + 2 * t;
            int c  = coff + nt * 8 + 2 * t;
            float bx = bp[cb], by = bp[cb + 1];
            if (r0 < NN) {
                float2 v = make_float2(acc[mt][nt][0] + bx, acc[mt][nt][1] + by);
                *(float2*)(obase + (size_t)r0 * DD + c) = v;
            }
            if (r0 + 8 < NN) {
                float2 v = make_float2(acc[mt][nt][2] + bx, acc[mt][nt][3] + by);
                *(float2*)(obase + (size_t)(r0 + 8) * DD + c) = v;
            }
        }
    }
}

// ---------------- GAT edge aggregation ----------------
// one warp per dst node; lane = slot(lane>>3), head(lane&7); each lane owns a full head
// fixed-shift softmax: shift = logit of first edge (cancels exactly in softmax)
__device__ __forceinline__ float lrl(float z) { return z > 0.f ? z : 0.2f * z; }

__global__ __launch_bounds__(256) void gat_kernel(const float* __restrict__ attb,
                                                  const float* __restrict__ biasb,
                                                  int outbuf, int round_out) {
    int gw = (blockIdx.x * blockDim.x + threadIdx.x) >> 5;
    int lane = threadIdx.x & 31;
    if (gw >= NN) return;
    float* hout = (outbuf == 0) ? g_bufA : g_bufB;

    int slot = lane >> 3, h = lane & 7;
    const float4* ap = (const float4*)(attb + h * 16);
    float4 at0 = ap[0], at1 = ap[1], at2 = ap[2], at3 = ap[3];
    const float4* xp = (const float4*)(g_xr + (size_t)gw * DD + h * 16);
    float4 xr0 = xp[0], xr1 = xp[1], xr2 = xp[2], xr3 = xp[3];

    int jb = g_rowptr[gw], je = g_rowptr[gw + 1];

#define DOT16(dst, p0, p1, p2, p3)                                             \
    {                                                                          \
        float dd_ = 0.f;                                                       \
        dd_ += at0.x * lrl(p0.x + xr0.x); dd_ += at0.y * lrl(p0.y + xr0.y);    \
        dd_ += at0.z * lrl(p0.z + xr0.z); dd_ += at0.w * lrl(p0.w + xr0.w);    \
        dd_ += at1.x * lrl(p1.x + xr1.x); dd_ += at1.y * lrl(p1.y + xr1.y);    \
        dd_ += at1.z * lrl(p1.z + xr1.z); dd_ += at1.w * lrl(p1.w + xr1.w);    \
        dd_ += at2.x * lrl(p2.x + xr2.x); dd_ += at2.y * lrl(p2.y + xr2.y);    \
        dd_ += at2.z * lrl(p2.z + xr2.z); dd_ += at2.w * lrl(p2.w + xr2.w);    \
        dd_ += at3.x * lrl(p3.x + xr3.x); dd_ += at3.y * lrl(p3.y + xr3.y);    \
        dd_ += at3.z * lrl(p3.z + xr3.z); dd_ += at3.w * lrl(p3.w + xr3.w);    \
        dst = dd_;                                                             \
    }

    // prologue: shift = logit of first edge (every lane computes it for its head)
    float m;
    {
        int src0 = g_esrc[jb];
        const float4* lp = (const float4*)(g_xl + (size_t)src0 * DD + h * 16);
        float4 x0 = lp[0], x1 = lp[1], x2 = lp[2], x3 = lp[3];
        DOT16(m, x0, x1, x2, x3);
    }

    float s = 0.f;
    float4 a0 = make_float4(0.f, 0.f, 0.f, 0.f), a1 = a0, a2 = a0, a3 = a0;

    int nIter = (je - jb + 3) >> 2;
    for (int it = 0; it < nIter; it++) {
        int j = jb + it * 4 + slot;
        bool act = (j < je);
        int jj = act ? j : (je - 1);
        int src = g_esrc[jj];
        const float4* lp = (const float4*)(g_xl + (size_t)src * DD + h * 16);
        float4 x0 = lp[0], x1 = lp[1], x2 = lp[2], x3 = lp[3];

        float d;
        DOT16(d, x0, x1, x2, x3);
        float p = act ? __expf(d - m) : 0.f;
        s += p;
        a0.x += p * x0.x; a0.y += p * x0.y; a0.z += p * x0.z; a0.w += p * x0.w;
        a1.x += p * x1.x; a1.y += p * x1.y; a1.z += p * x1.z; a1.w += p * x1.w;
        a2.x += p * x2.x; a2.y += p * x2.y; a2.z += p * x2.z; a2.w += p * x2.w;
        a3.x += p * x3.x; a3.y += p * x3.y; a3.z += p * x3.z; a3.w += p * x3.w;
    }
#undef DOT16

    // merge 4 slots: plain sums
#pragma unroll
    for (int off = 8; off <= 16; off <<= 1) {
        s += __shfl_xor_sync(0xffffffffu, s, off);
#define MRG(c) c += __shfl_xor_sync(0xffffffffu, c, off)
        MRG(a0.x); MRG(a0.y); MRG(a0.z); MRG(a0.w);
        MRG(a1.x); MRG(a1.y); MRG(a1.z); MRG(a1.w);
        MRG(a2.x); MRG(a2.y); MRG(a2.z); MRG(a2.w);
        MRG(a3.x); MRG(a3.y); MRG(a3.z); MRG(a3.w);
#undef MRG
    }

    if (slot == 0) {
        float inv = 1.f / s;
        const float4* bp = (const float4*)(biasb + h * 16);
        float4 b0 = bp[0], b1 = bp[1], b2 = bp[2], b3 = bp[3];
        float4 o0, o1, o2, o3;
#define FIN(o, a, b) \
        o.x = a.x * inv + b.x; o.x = o.x > 0.f ? o.x : (__expf(o.x) - 1.f); \
        o.y = a.y * inv + b.y; o.y = o.y > 0.f ? o.y : (__expf(o.y) - 1.f); \
        o.z = a.z * inv + b.z; o.z = o.z > 0.f ? o.z : (__expf(o.z) - 1.f); \
        o.w = a.w * inv + b.w; o.w = o.w > 0.f ? o.w : (__expf(o.w) - 1.f)
        FIN(o0, a0, b0); FIN(o1, a1, b1); FIN(o2, a2, b2); FIN(o3, a3, b3);
#undef FIN
        if (round_out) {
            o0.x = f2tf32f(o0.x); o0.y = f2tf32f(o0.y); o0.z = f2tf32f(o0.z); o0.w = f2tf32f(o0.w);
            o1.x = f2tf32f(o1.x); o1.y = f2tf32f(o1.y); o1.z = f2tf32f(o1.z); o1.w = f2tf32f(o1.w);
            o2.x = f2tf32f(o2.x); o2.y = f2tf32f(o2.y); o2.z = f2tf32f(o2.z); o2.w = f2tf32f(o2.w);
            o3.x = f2tf32f(o3.x); o3.y = f2tf32f(o3.y); o3.z = f2tf32f(o3.z); o3.w = f2tf32f(o3.w);
        }
        float4* op = (float4*)(hout + (size_t)gw * DD + h * 16);
        op[0] = o0; op[1] = o1; op[2] = o2; op[3] = o3;
    }
}

// ---------------- global mean pool: run-length accumulate (batch is sorted) ----------------
__global__ __launch_bounds__(128) void pool_kernel(const int* __restrict__ batch) {
    int ch = threadIdx.x;                  // 0..127
    int n0 = blockIdx.x * 128;
    int nEnd = n0 + 128; if (nEnd > NN) nEnd = NN;
    if (n0 >= NN) return;

    int cur = batch[n0];
    float acc = 0.f;
    int runlen = 0;
    for (int nd = n0; nd < nEnd; nd++) {
        int gidx = batch[nd];
        if (gidx != cur) {
            atomicAdd(&g_pool[cur * DD + ch], acc);
            if (ch == 0) atomicAdd(&g_pcnt[cur], (float)runlen);
            acc = 0.f; runlen = 0; cur = gidx;
        }
        acc += g_bufA[(size_t)nd * DD + ch];
        runlen++;
    }
    atomicAdd(&g_pool[cur * DD + ch], acc);
    if (ch == 0) atomicAdd(&g_pcnt[cur], (float)runlen);
}

// ---------------- classifier + log_softmax ----------------
__global__ void cls_kernel(const float* __restrict__ Wout,
                           const float* __restrict__ bout,
                           float* __restrict__ out) {
    __shared__ float slog[NG][NC];
    __shared__ float srow[NG];
    int t = threadIdx.x;
    if (t < NG * NC) {
        int g = t / NC, c = t % NC;
        float inv = 1.f / fmaxf(g_pcnt[g], 1.f);
        float acc = 0.f;
        for (int k = 0; k < DD; k++) acc += g_pool[g * DD + k] * Wout[k * NC + c];
        slog[g][c] = acc * inv + bout[c];
    }
    __syncthreads();
    if (t < NG) {
        float mx = -3.0e38f;
        for (int c = 0; c < NC; c++) mx = fmaxf(mx, slog[t][c]);
        float ssum = 0.f;
        for (int c = 0; c < NC; c++) ssum += expf(slog[t][c] - mx);
        srow[t] = mx + logf(ssum);
    }
    __syncthreads();
    if (t < NG * NC) out[t] = slog[t / NC][t % NC] - srow[t / NC];
}

// ---------------- driver ----------------
extern "C" void kernel_launch(void* const* d_in, const int* in_sizes, int n_in,
                              void* d_out, int out_size) {
    const float* x     = (const float*)d_in[0];
    const int*   ei    = (const int*)  d_in[1];
    const int*   batch = (const int*)  d_in[2];
    const float* Wl    = (const float*)d_in[3];
    const float* bl    = (const float*)d_in[4];
    const float* Wr    = (const float*)d_in[5];
    const float* br    = (const float*)d_in[6];
    const float* att   = (const float*)d_in[7];
    const float* bias  = (const float*)d_in[8];
    const float* Wout  = (const float*)d_in[9];
    const float* bout  = (const float*)d_in[10];
    float* out = (float*)d_out;

    init_kernel<<<(NN + 255) / 256, 256>>>();
    count_kernel<<<(NE + 255) / 256, 256>>>(ei);
    scan1_kernel<<<SCAN_BLOCKS, 1024>>>();
    scan2_kernel<<<1, 32>>>();
    scan3_kernel<<<SCAN_BLOCKS, 1024>>>();
    scatter_kernel<<<(NE + 255) / 256, 256>>>(ei);
    pack_kernel<<<(NL * DD * 256 + NL * 256 + 255) / 256, 256>>>(Wl, bl, Wr, br);
    roundx_kernel<<<(NN * DD / 4 + 255) / 256, 256>>>(x);

    dim3 ggrid((NN + GBM - 1) / GBM, 4);
    for (int l = 0; l < NL; l++) {
        gemm_tc_kernel<<<ggrid, 256>>>(l);
        int outbuf = (l % 2 == 0) ? 0 : 1;
        int round_out = (l < NL - 1) ? 1 : 0;
        gat_kernel<<<(NN * 32 + 255) / 256, 256>>>(att + l * DD, bias + l * DD, outbuf, round_out);
    }

    pool_kernel<<<(NN + 127) / 128, 128>>>(batch);
    cls_kernel<<<1, 640>>>(Wout, bout, out);
}